// round 3
// baseline (speedup 1.0000x reference)
#include <cuda_runtime.h>
#include <math.h>

#define BB 2
#define CC 64
#define HH 256
#define WW 256
#define HWW (HH*WW)

// ---- scratch (device globals; no runtime allocation allowed) ----
__device__ float g_om[BB*27*HWW];       // offset/mask conv output
__device__ float g_h1[BB*CC*HWW];       // after DCN + bn1 + relu
__device__ float g_h2[BB*CC*HWW];       // after conv_h + bn2 + relu
__device__ float g_h3[BB*CC*HWW];       // after conv_w + bn3 + relu
__device__ float g_wT_om[CC*9*32];      // [c][tap][ocpad32]
__device__ float g_wT_dcn[CC*9*CC];     // [c][tap][oc]
__device__ float g_wT_h[CC*9*CC];
__device__ float g_wT_w[CC*9*CC];

// ---------------------------------------------------------------------------
// Weight transpose: src [OC][C][3][3] -> dst [(c*9+tap)*OCPAD + oc]
// ---------------------------------------------------------------------------
__global__ void prep_weights_kernel(const float* __restrict__ w_om,
                                    const float* __restrict__ w_dcn,
                                    const float* __restrict__ w_h,
                                    const float* __restrict__ w_w) {
    const int i0 = blockIdx.x * blockDim.x + threadIdx.x;
    const int stride = gridDim.x * blockDim.x;
    for (int i = i0; i < CC*9*32; i += stride) {
        int oc = i & 31; int ct = i >> 5; int c = ct / 9, tap = ct % 9;
        g_wT_om[i] = (oc < 27) ? w_om[(oc*CC + c)*9 + tap] : 0.f;
    }
    for (int i = i0; i < CC*9*CC; i += stride) {
        int oc = i & 63; int ct = i >> 6; int c = ct / 9, tap = ct % 9;
        int s = (oc*CC + c)*9 + tap;
        g_wT_dcn[i] = w_dcn[s];
        g_wT_h[i]   = w_h[s];
        g_wT_w[i]   = w_w[s];
    }
}

// ---------------------------------------------------------------------------
// Offset/mask conv: x[64ch] -> g_om[27ch], 3x3 pad1, + bias.
// Block: 256 thr = 32 px-groups x 8 oc-groups; per-thread 4px x 4oc.
// ---------------------------------------------------------------------------
__global__ void __launch_bounds__(256)
conv_om_kernel(const float* __restrict__ x,
               const float* __restrict__ b_om) {
    const int x0 = blockIdx.x * 128;
    const int y  = blockIdx.y;
    const int b  = blockIdx.z;
    const int tid = threadIdx.x;
    const int pxg = tid & 31, ocg = tid >> 5;
    const int px0 = pxg * 4, oc0 = ocg * 4;
    const int NCOL = 130;

    __shared__ float s_rows[3][132];
    __shared__ float s_w[9*32];

    float acc[4][4] = {};

    for (int c = 0; c < CC; c++) {
        __syncthreads();
        const float* xc = x + ((size_t)(b*CC + c))*HWW;
        for (int i = tid; i < 3*NCOL; i += 256) {
            int r = i / NCOL, col = i - r*NCOL;
            int yy = y + r - 1, xx = x0 - 1 + col;
            float v = 0.f;
            if ((unsigned)yy < HH && (unsigned)xx < WW) v = xc[yy*WW + xx];
            s_rows[r][col] = v;
        }
        const float* wp = g_wT_om + c*9*32;
        for (int i = tid; i < 288; i += 256) s_w[i] = wp[i];
        __syncthreads();
#pragma unroll
        for (int ky = 0; ky < 3; ky++) {
            float iv[6];
#pragma unroll
            for (int j = 0; j < 6; j++) iv[j] = s_rows[ky][px0 + j];
#pragma unroll
            for (int kx = 0; kx < 3; kx++) {
                const float* wrow = s_w + (ky*3+kx)*32 + oc0;
                float wv[4];
#pragma unroll
                for (int i = 0; i < 4; i++) wv[i] = wrow[i];
#pragma unroll
                for (int i = 0; i < 4; i++)
#pragma unroll
                    for (int j = 0; j < 4; j++)
                        acc[i][j] = fmaf(wv[i], iv[j+kx], acc[i][j]);
            }
        }
    }
#pragma unroll
    for (int i = 0; i < 4; i++) {
        int oc = oc0 + i;
        if (oc < 27) {
            float bo = b_om[oc];
            float* op = g_om + ((size_t)(b*27 + oc))*HWW + y*WW + x0 + px0;
#pragma unroll
            for (int j = 0; j < 4; j++) op[j] = acc[i][j] + bo;
        }
    }
}

// ---------------------------------------------------------------------------
// Modulated deformable conv (DCNv2) + bn1 + relu -> g_h1.
// ---------------------------------------------------------------------------
__global__ void __launch_bounds__(256)
dcn_kernel(const float* __restrict__ x,
           const float* __restrict__ bias,
           const float* __restrict__ bg, const float* __restrict__ bb,
           const float* __restrict__ bm, const float* __restrict__ bv) {
    const int x0 = blockIdx.x * 128;
    const int y  = blockIdx.y;
    const int b  = blockIdx.z;
    const int tid = threadIdx.x;
    const int pxg = tid & 31, ocg = tid >> 5;
    const int px0 = pxg * 4, oc0 = ocg * 8;

    __shared__ int   s_idx[9*128][4];
    __shared__ float s_gw [9*128][4];
    __shared__ float s_cols[9][128];
    __shared__ float s_w[9*64];

    // geometry: bilinear corner indices + (mask * bilinear * valid) weights
    for (int s = tid; s < 9*128; s += 256) {
        int k = s >> 7, px = s & 127;
        int xx = x0 + px;
        float o1 = g_om[((b*27 +      k)*HH + y)*WW + xx];
        float o2 = g_om[((b*27 +  9 + k)*HH + y)*WW + xx];
        float ml = g_om[((b*27 + 18 + k)*HH + y)*WW + xx];
        float m  = 1.f / (1.f + expf(-ml));
        float py  = (float)(y  + (k/3) - 1) + o1;
        float pxf = (float)(xx + (k%3) - 1) + o2;
        float fy = floorf(py), fx = floorf(pxf);
        float wy1 = py - fy, wx1 = pxf - fx;
        int iy0 = (int)fy, ix0 = (int)fx;
#pragma unroll
        for (int j = 0; j < 4; j++) {
            int dy = j >> 1, dx = j & 1;
            int yi = iy0 + dy, xi = ix0 + dx;
            bool valid = ((unsigned)yi < HH) && ((unsigned)xi < WW);
            float wgt = (dy ? wy1 : 1.f - wy1) * (dx ? wx1 : 1.f - wx1);
            s_gw[s][j]  = valid ? m * wgt : 0.f;
            int yc = min(max(yi, 0), HH-1);
            int xc = min(max(xi, 0), WW-1);
            s_idx[s][j] = yc*WW + xc;
        }
    }

    float acc[8][4] = {};

    for (int c = 0; c < CC; c++) {
        __syncthreads();
        const float* xc = x + ((size_t)(b*CC + c))*HWW;
        for (int s = tid; s < 9*128; s += 256) {
            float v = s_gw[s][0]*xc[s_idx[s][0]] + s_gw[s][1]*xc[s_idx[s][1]]
                    + s_gw[s][2]*xc[s_idx[s][2]] + s_gw[s][3]*xc[s_idx[s][3]];
            s_cols[s >> 7][s & 127] = v;
        }
        const float* wp = g_wT_dcn + c*576;
        for (int i = tid; i < 576; i += 256) s_w[i] = wp[i];
        __syncthreads();
#pragma unroll
        for (int k = 0; k < 9; k++) {
            float iv[4];
#pragma unroll
            for (int j = 0; j < 4; j++) iv[j] = s_cols[k][px0 + j];
            const float* wrow = s_w + k*64 + oc0;
            float wv[8];
#pragma unroll
            for (int i = 0; i < 8; i++) wv[i] = wrow[i];
#pragma unroll
            for (int i = 0; i < 8; i++)
#pragma unroll
                for (int j = 0; j < 4; j++)
                    acc[i][j] = fmaf(wv[i], iv[j], acc[i][j]);
        }
    }
#pragma unroll
    for (int i = 0; i < 8; i++) {
        int oc = oc0 + i;
        float s = bg[oc] * rsqrtf(bv[oc] + 1e-5f);
        float d = (bias[oc] - bm[oc]) * s + bb[oc];
        float* op = g_h1 + ((size_t)(b*CC + oc))*HWW + y*WW + x0 + px0;
#pragma unroll
        for (int j = 0; j < 4; j++) {
            float v = fmaf(acc[i][j], s, d);
            op[j] = v > 0.f ? v : 0.f;
        }
    }
}

// ---------------------------------------------------------------------------
// Generic 64->64 3x3 conv (templated dilation) + bn + relu.
// ---------------------------------------------------------------------------
template<int DIL>
__global__ void __launch_bounds__(256)
conv64_kernel(const float* __restrict__ in, const float* __restrict__ wT,
              const float* __restrict__ bias,
              const float* __restrict__ bg, const float* __restrict__ bb,
              const float* __restrict__ bm, const float* __restrict__ bv,
              float* __restrict__ out) {
    const int x0 = blockIdx.x * 128;
    const int y  = blockIdx.y;
    const int b  = blockIdx.z;
    const int tid = threadIdx.x;
    const int pxg = tid & 31, ocg = tid >> 5;
    const int px0 = pxg * 4, oc0 = ocg * 8;
    constexpr int NCOL = 128 + 2*DIL;

    __shared__ float s_rows[3][136];
    __shared__ float s_w[9*64];

    float acc[8][4] = {};

    for (int c = 0; c < CC; c++) {
        __syncthreads();
        const float* inc = in + ((size_t)(b*CC + c))*HWW;
        for (int i = tid; i < 3*NCOL; i += 256) {
            int r = i / NCOL, col = i - r*NCOL;
            int yy = y + (r-1)*DIL, xx = x0 - DIL + col;
            float v = 0.f;
            if ((unsigned)yy < HH && (unsigned)xx < WW) v = inc[yy*WW + xx];
            s_rows[r][col] = v;
        }
        const float* wp = wT + c*576;
        for (int i = tid; i < 576; i += 256) s_w[i] = wp[i];
        __syncthreads();
#pragma unroll
        for (int ky = 0; ky < 3; ky++) {
            float iv[4 + 2*DIL];
#pragma unroll
            for (int j = 0; j < 4 + 2*DIL; j++) iv[j] = s_rows[ky][px0 + j];
#pragma unroll
            for (int kx = 0; kx < 3; kx++) {
                const float* wrow = s_w + (ky*3+kx)*64 + oc0;
                float wv[8];
#pragma unroll
                for (int i = 0; i < 8; i++) wv[i] = wrow[i];
#pragma unroll
                for (int i = 0; i < 8; i++)
#pragma unroll
                    for (int j = 0; j < 4; j++)
                        acc[i][j] = fmaf(wv[i], iv[j + kx*DIL], acc[i][j]);
            }
        }
    }
#pragma unroll
    for (int i = 0; i < 8; i++) {
        int oc = oc0 + i;
        float s = bg[oc] * rsqrtf(bv[oc] + 1e-5f);
        float d = (bias[oc] - bm[oc]) * s + bb[oc];
        float* op = out + ((size_t)(b*CC + oc))*HWW + y*WW + x0 + px0;
#pragma unroll
        for (int j = 0; j < 4; j++) {
            float v = fmaf(acc[i][j], s, d);
            op[j] = v > 0.f ? v : 0.f;
        }
    }
}

// ---------------------------------------------------------------------------
// Final 64->1 3x3 conv pad1 + sigmoid + clip.
// ---------------------------------------------------------------------------
__global__ void __launch_bounds__(256)
final_kernel(const float* __restrict__ w3, const float* __restrict__ b3,
             float* __restrict__ out) {
    const int y = blockIdx.x;
    const int b = blockIdx.y;
    const int tid = threadIdx.x;  // 256 = W

    __shared__ float s_rows[3][260];
    __shared__ float s_w3[576];
    for (int i = tid; i < 576; i += 256) s_w3[i] = w3[i];

    float acc = 0.f;
    for (int c = 0; c < CC; c++) {
        __syncthreads();
        const float* hc = g_h3 + ((size_t)(b*CC + c))*HWW;
        for (int i = tid; i < 3*258; i += 256) {
            int r = i / 258, col = i - r*258;
            int yy = y + r - 1, xx = col - 1;
            float v = 0.f;
            if ((unsigned)yy < HH && (unsigned)xx < WW) v = hc[yy*WW + xx];
            s_rows[r][col] = v;
        }
        __syncthreads();
        const float* wc = s_w3 + c*9;
#pragma unroll
        for (int ky = 0; ky < 3; ky++)
#pragma unroll
            for (int kx = 0; kx < 3; kx++)
                acc = fmaf(wc[ky*3+kx], s_rows[ky][tid + kx], acc);
    }
    float v = acc + b3[0];
    float sg = 1.f / (1.f + expf(-v));
    sg = fminf(fmaxf(sg, 1e-4f), 1.f - 1e-4f);
    out[((size_t)b*HH + y)*WW + tid] = sg;
}

// ---------------------------------------------------------------------------
extern "C" void kernel_launch(void* const* d_in, const int* in_sizes, int n_in,
                              void* d_out, int out_size) {
    (void)n_in; (void)out_size;
    const float* x     = (const float*)d_in[0];
    const float* w_om  = (const float*)d_in[1];
    const float* b_om  = (const float*)d_in[2];
    const float* w_dcn = (const float*)d_in[3];
    const float* b_dcn = (const float*)d_in[4];
    const float* bn1g  = (const float*)d_in[5];
    const float* bn1b  = (const float*)d_in[6];
    const float* bn1m  = (const float*)d_in[7];
    const float* bn1v  = (const float*)d_in[8];

    // Two possible orderings:
    //  (a) setup_inputs dict order: bn2(9..12), bn3(13..16), w_h(17), b_h(18),
    //      w_w(19), b_w(20), w3(21), b3(22)
    //  (b) reference signature order: w_h(9), b_h(10), bn2(11..14), ...
    // Disambiguate via in_sizes: in dict order, in_sizes[9] == 64 (bn2_g);
    // in signature order, in_sizes[9] == 64*64*9 (w_h).
    const float *w_h, *b_h, *w_w, *b_w, *w3, *b3;
    const float *bn2g, *bn2b, *bn2m, *bn2v, *bn3g, *bn3b, *bn3m, *bn3v;
    if (in_sizes[9] == CC) {
        // dict order
        bn2g = (const float*)d_in[9];  bn2b = (const float*)d_in[10];
        bn2m = (const float*)d_in[11]; bn2v = (const float*)d_in[12];
        bn3g = (const float*)d_in[13]; bn3b = (const float*)d_in[14];
        bn3m = (const float*)d_in[15]; bn3v = (const float*)d_in[16];
        w_h  = (const float*)d_in[17]; b_h  = (const float*)d_in[18];
        w_w  = (const float*)d_in[19]; b_w  = (const float*)d_in[20];
        w3   = (const float*)d_in[21]; b3   = (const float*)d_in[22];
    } else {
        // signature order
        w_h  = (const float*)d_in[9];  b_h  = (const float*)d_in[10];
        bn2g = (const float*)d_in[11]; bn2b = (const float*)d_in[12];
        bn2m = (const float*)d_in[13]; bn2v = (const float*)d_in[14];
        w_w  = (const float*)d_in[15]; b_w  = (const float*)d_in[16];
        bn3g = (const float*)d_in[17]; bn3b = (const float*)d_in[18];
        bn3m = (const float*)d_in[19]; bn3v = (const float*)d_in[20];
        w3   = (const float*)d_in[21]; b3   = (const float*)d_in[22];
    }
    float* out = (float*)d_out;

    float *p_h1, *p_h2, *p_h3, *p_wT_h, *p_wT_w;
    cudaGetSymbolAddress((void**)&p_h1,   g_h1);
    cudaGetSymbolAddress((void**)&p_h2,   g_h2);
    cudaGetSymbolAddress((void**)&p_h3,   g_h3);
    cudaGetSymbolAddress((void**)&p_wT_h, g_wT_h);
    cudaGetSymbolAddress((void**)&p_wT_w, g_wT_w);

    prep_weights_kernel<<<72, 256>>>(w_om, w_dcn, w_h, w_w);

    dim3 gridc(WW/128, HH, BB);
    conv_om_kernel<<<gridc, 256>>>(x, b_om);
    dcn_kernel<<<gridc, 256>>>(x, b_dcn, bn1g, bn1b, bn1m, bn1v);
    conv64_kernel<2><<<gridc, 256>>>(p_h1, p_wT_h, b_h, bn2g, bn2b, bn2m, bn2v, p_h2);
    conv64_kernel<2><<<gridc, 256>>>(p_h2, p_wT_w, b_w, bn3g, bn3b, bn3m, bn3v, p_h3);
    final_kernel<<<dim3(HH, BB), 256>>>(w3, b3, out);
}